// round 5
// baseline (speedup 1.0000x reference)
#include <cuda_runtime.h>
#include <stdint.h>

// m=n=8192, k=64 fixed. Output dtype: float32 (quantized integer values).
#define COLS    8192
#define KDIM    64
#define GRID    148
#define THREADS 256
#define XPAD    68                      // padded chunk stride (floats)
#define BUF_FLOATS (2*128*XPAD)         // one row-pair staged (2 rows x 128 chunks)
#define SMEM_FLOATS (KDIM*KDIM + 2*BUF_FLOATS)
#define SMEM_BYTES  (SMEM_FLOATS * 4)   // 16384 + 139264 = 155648 B

#define FMA_PAIR(accref, xx, hp) \
    asm("fma.rn.f32x2 %0, %1, %2, %0;" : "+l"(accref) : "l"(xx), "l"(hp))

#define CPA16(dst_ptr, src_ptr) \
    asm volatile("cp.async.cg.shared.global [%0], [%1], 16;" \
                 :: "r"((uint32_t)__cvta_generic_to_shared(dst_ptr)), "l"(src_ptr))

__device__ __forceinline__ void stage_pair(float* dst, const float* src, int t)
{
    // 2 rows = 16384 floats -> chunk-padded [256][XPAD]
    #pragma unroll
    for (int p = 0; p < 16; ++p) {
        const int n = p * (THREADS * 4) + t * 4;
        CPA16(dst + (n >> 6) * XPAD + (n & 63), src + n);
    }
}

__global__ __launch_bounds__(THREADS, 1)
void bdq4_kernel(const float* __restrict__ x, const float* __restrict__ hmat,
                 float* __restrict__ out, int npair)
{
    extern __shared__ float smem[];
    float* h_s = smem;                      // 64*64 floats
    float* x_s = smem + KDIM * KDIM;        // 2 buffers x BUF_FLOATS
    __shared__ float red0[THREADS / 32], red1[THREADS / 32];

    const int t   = threadIdx.x;
    const int bid = blockIdx.x;
    const int g   = t >> 3;                 // chunk-group 0..31
    const int jlo = (t & 7) << 2;           // cols jlo..jlo+3 and jlo+32..+35

    // ---- prologue: group0 = h + pair(bid) -> buf0 ; group1 = pair(bid+GRID) -> buf1 ----
    #pragma unroll
    for (int p = 0; p < 4; ++p) {
        const int n = p * (THREADS * 4) + t * 4;
        CPA16(h_s + n, hmat + n);
    }
    if (bid < npair)
        stage_pair(x_s, x + (long)(2 * bid) * COLS, t);
    asm volatile("cp.async.commit_group;");
    if (bid + GRID < npair)
        stage_pair(x_s + BUF_FLOATS, x + (long)(2 * (bid + GRID)) * COLS, t);
    asm volatile("cp.async.commit_group;");

    int it = 0;
    for (int pair = bid; pair < npair; pair += GRID, ++it) {
        const int buf = it & 1;

        asm volatile("cp.async.wait_group 1;");   // group(it) complete
        __syncthreads();

        // ================= merged 2-row compute: 8 sets, h amortized x8 =================
        unsigned long long acc[8][4];
        #pragma unroll
        for (int s = 0; s < 8; ++s)
            #pragma unroll
            for (int p = 0; p < 4; ++p)
                acc[s][p] = 0ull;

        const float* xb = x_s + buf * BUF_FLOATS + g * XPAD;

        #pragma unroll 4
        for (int i4 = 0; i4 < KDIM; i4 += 4) {
            float4 xv[8];
            #pragma unroll
            for (int s = 0; s < 8; ++s) {
                const int r = s >> 2, q = s & 3;
                xv[s] = *(const float4*)(xb + (r * 128 + q * 32) * XPAD + i4);
            }
            #pragma unroll
            for (int di = 0; di < 4; ++di) {
                const float* hr = h_s + (i4 + di) * KDIM + jlo;
                const ulonglong2 hA = *(const ulonglong2*)(hr);       // cols jlo..+3
                const ulonglong2 hB = *(const ulonglong2*)(hr + 32);  // cols jlo+32..+35
                #pragma unroll
                for (int s = 0; s < 8; ++s) {
                    const float xi = (di == 0) ? xv[s].x : (di == 1) ? xv[s].y
                                   : (di == 2) ? xv[s].z : xv[s].w;
                    unsigned long long xx;
                    asm("mov.b64 %0, {%1, %1};" : "=l"(xx) : "f"(xi));
                    FMA_PAIR(acc[s][0], xx, hA.x);
                    FMA_PAIR(acc[s][1], xx, hA.y);
                    FMA_PAIR(acc[s][2], xx, hB.x);
                    FMA_PAIR(acc[s][3], xx, hB.y);
                }
            }
        }

        // ---- unpack + per-row absmax ----
        float rv[8][8];
        float m0 = 0.0f, m1 = 0.0f;
        #pragma unroll
        for (int s = 0; s < 8; ++s) {
            float mm = 0.0f;
            #pragma unroll
            for (int p = 0; p < 4; ++p) {
                float lo, hi;
                asm("mov.b64 {%0, %1}, %2;" : "=f"(lo), "=f"(hi) : "l"(acc[s][p]));
                rv[s][2 * p]     = lo;
                rv[s][2 * p + 1] = hi;
                mm = fmaxf(mm, fmaxf(fabsf(lo), fabsf(hi)));
            }
            if (s < 4) m0 = fmaxf(m0, mm); else m1 = fmaxf(m1, mm);
        }
        #pragma unroll
        for (int o = 16; o > 0; o >>= 1) {
            m0 = fmaxf(m0, __shfl_xor_sync(0xffffffffu, m0, o));
            m1 = fmaxf(m1, __shfl_xor_sync(0xffffffffu, m1, o));
        }
        if ((t & 31) == 0) { red0[t >> 5] = m0; red1[t >> 5] = m1; }
        __syncthreads();                      // also: all buffer reads complete

        // ---- prefetch pair+2*GRID into this (now free) buffer ----
        if (pair + 2 * GRID < npair)
            stage_pair(x_s + buf * BUF_FLOATS,
                       x + (long)(2 * (pair + 2 * GRID)) * COLS, t);
        asm volatile("cp.async.commit_group;"); // (possibly empty; keeps numbering)

        // ---- every thread finishes the reduction locally (identical results) ----
        float a0 = red0[0], a1 = red1[0];
        #pragma unroll
        for (int w = 1; w < THREADS / 32; ++w) {
            a0 = fmaxf(a0, red0[w]);
            a1 = fmaxf(a1, red1[w]);
        }
        const float inv0 = (a0 == 0.0f) ? 1.0f : __fdiv_rn(127.0f, a0);
        const float inv1 = (a1 == 0.0f) ? 1.0f : __fdiv_rn(127.0f, a1);

        // ---- quantize (round-half-even) + store float32 ----
        const long row0 = (long)(2 * pair);
        #pragma unroll
        for (int s = 0; s < 8; ++s) {
            const int r = s >> 2, q = s & 3;
            const float inv = (r == 0) ? inv0 : inv1;
            float qv[8];
            #pragma unroll
            for (int e = 0; e < 8; ++e) {
                float qf = rintf(rv[s][e] * inv);
                qv[e] = fminf(fmaxf(qf, -128.0f), 127.0f);
            }
            float* dst = out + (row0 + r) * (long)COLS + (q * 32 + g) * KDIM + jlo;
            *(float4*)(dst)      = make_float4(qv[0], qv[1], qv[2], qv[3]);
            *(float4*)(dst + 32) = make_float4(qv[4], qv[5], qv[6], qv[7]);
        }
    }
}

extern "C" void kernel_launch(void* const* d_in, const int* in_sizes, int n_in,
                              void* d_out, int out_size)
{
    const float* x;
    const float* h;
    long x_elems;
    if (in_sizes[0] > in_sizes[1]) {
        x = (const float*)d_in[0]; h = (const float*)d_in[1]; x_elems = in_sizes[0];
    } else {
        x = (const float*)d_in[1]; h = (const float*)d_in[0]; x_elems = in_sizes[1];
    }
    const int rows  = (int)(x_elems / COLS);
    const int npair = rows / 2;

    cudaFuncSetAttribute(bdq4_kernel, cudaFuncAttributeMaxDynamicSharedMemorySize, SMEM_BYTES);
    bdq4_kernel<<<GRID, THREADS, SMEM_BYTES>>>(x, h, (float*)d_out, npair);
}